// round 12
// baseline (speedup 1.0000x reference)
#include <cuda_runtime.h>
#include <cstdint>

#define S_LEN  2048
#define HEADS  32
#define DDIM   64
#define BQ     64
#define BK     64
#define NTILES (S_LEN / BK)   // 32
#define MASKW  (S_LEN / 32)   // 64 mask words per row

#define SLOTW  136                    // pair-slot stride in u32 (2*64 + 8 pad)
#define KIMG_W (16 * SLOTW)           // 2176 u32 = 8704 B (one K or V tile image)
#define TILE_W (2 * KIMG_W)           // 4352 u32 = 17408 B (K + V)
#define TILE_BYTES (TILE_W * 4)
#define SMEM_U32 (2 * TILE_W)         // 34816 B (double buffer; reused as scratch at end)

__device__ uint32_t g_maskbits[S_LEN * MASKW];                 // 512 KB
__device__ uint32_t g_KVp[(size_t)HEADS * NTILES * TILE_W];    // ~17.8 MB packed K+V (fp16)

__device__ __forceinline__ uint32_t packh2(float lo, float hi) {
    uint32_t r;
    asm("cvt.rn.f16x2.f32 %0, %1, %2;" : "=r"(r) : "f"(hi), "f"(lo));
    return r;
}
__device__ __forceinline__ float ex2f(float x) {
    float r;
    asm("ex2.approx.f32 %0, %1;" : "=f"(r) : "f"(x));
    return r;
}
__device__ __forceinline__ void mma_f16(float* d, const uint32_t* a, uint32_t b0, uint32_t b1) {
    asm volatile(
        "mma.sync.aligned.m16n8k16.row.col.f32.f16.f16.f32 "
        "{%0,%1,%2,%3}, {%4,%5,%6,%7}, {%8,%9}, {%0,%1,%2,%3};"
        : "+f"(d[0]), "+f"(d[1]), "+f"(d[2]), "+f"(d[3])
        : "r"(a[0]), "r"(a[1]), "r"(a[2]), "r"(a[3]), "r"(b0), "r"(b1));
}
__device__ __forceinline__ uint32_t smem_u32(const void* p) {
    uint32_t a;
    asm("{ .reg .u64 t; cvta.to.shared.u64 t, %1; cvt.u32.u64 %0, t; }" : "=r"(a) : "l"(p));
    return a;
}
__device__ __forceinline__ void cpa16(uint32_t s, const void* g) {
    asm volatile("cp.async.cg.shared.global [%0], [%1], 16;" :: "r"(s), "l"(g));
}
#define CP_COMMIT() asm volatile("cp.async.commit_group;" ::: "memory")
#define CP_WAIT1()  asm volatile("cp.async.wait_group 1;" ::: "memory")

// ---------------- mask -> bitmask pre-pass (1 thread = 1 word) ----------------
__global__ void mask_bits_kernel(const int* __restrict__ M) {
    const int w = blockIdx.x * 256 + threadIdx.x;
    const int4* p = (const int4*)(M + (size_t)w * 32);
    uint32_t bits = 0;
    #pragma unroll
    for (int i = 0; i < 8; ++i) {
        int4 v = p[i];
        bits |= (v.x != 0 ? 1u : 0u) << (4 * i + 0);
        bits |= (v.y != 0 ? 1u : 0u) << (4 * i + 1);
        bits |= (v.z != 0 ? 1u : 0u) << (4 * i + 2);
        bits |= (v.w != 0 ? 1u : 0u) << (4 * i + 3);
    }
    g_maskbits[w] = bits;
}

// ---------------- K/V pack pre-pass: fp16 pair-slot smem images ----------------
__global__ void kv_pack_kernel(const float* __restrict__ K, const float* __restrict__ V) {
    const int t = blockIdx.x, h = blockIdx.y;
    const int tid = threadIdx.x;
    const int r = tid & 63, sg = tid >> 6;
    const float* kbT = K + (size_t)h * S_LEN * DDIM + (size_t)t * BK * DDIM;
    const float* vbT = V + (size_t)h * S_LEN * DDIM + (size_t)t * BK * DDIM;
    uint32_t* kd = g_KVp + ((size_t)h * NTILES + t) * TILE_W;
    uint32_t* vd = kd + KIMG_W;

    #pragma unroll
    for (int si = 0; si < 4; ++si) {
        const int slot = 4 * si + sg;
        const int kk = slot >> 2, tg = slot & 3;
        const int c0 = 16 * kk + 2 * tg;
        float2 ka = *(const float2*)&kbT[(size_t)r * DDIM + c0];
        float2 kc = *(const float2*)&kbT[(size_t)r * DDIM + c0 + 8];
        *(uint2*)&kd[slot * SLOTW + 2 * r] =
            make_uint2(packh2(ka.x, ka.y), packh2(kc.x, kc.y));
        float v0 = vbT[(size_t)(c0 + 0) * DDIM + r];
        float v1 = vbT[(size_t)(c0 + 1) * DDIM + r];
        float v8 = vbT[(size_t)(c0 + 8) * DDIM + r];
        float v9 = vbT[(size_t)(c0 + 9) * DDIM + r];
        *(uint2*)&vd[slot * SLOTW + 2 * r] =
            make_uint2(packh2(v0, v1), packh2(v8, v9));
    }
}

// ---------------- main kernel: M=32 x N=32 warp tiles, key-split + end reduce ----
__global__ void __launch_bounds__(128, 2)
fa_f16s_kernel(const float* __restrict__ Q, float* __restrict__ O) {
    __shared__ uint32_t smem[SMEM_U32];
    const uint32_t sb = smem_u32(smem);

    const int tid  = threadIdx.x;
    const int wid  = tid >> 5, lane = tid & 31;
    const int g    = lane >> 2, tg = lane & 3;
    const int nh   = wid & 1;                // key half (0: keys 0-31, 1: 32-63)
    const int mg   = wid >> 1;               // row group (0: rows 0-31, 1: 32-63)
    const int bh   = blockIdx.y;
    const int q0   = blockIdx.x * BQ;
    const int rw   = mg * 32;                // warp's first local row

    const float* qb = Q + (size_t)bh * S_LEN * DDIM;
    float*       ob = O + (size_t)bh * S_LEN * DDIM;
    const char*  kvb = (const char*)(g_KVp + (size_t)bh * NTILES * TILE_W);

    // ---- Q fragments: 2 row-tiles x 4 k-steps x 4 regs = 32 regs ----
    uint32_t qfrag[2][4][4];
    #pragma unroll
    for (int rt = 0; rt < 2; ++rt) {
        const float* qr0 = &qb[(size_t)(q0 + rw + 16 * rt + g) * DDIM];
        const float* qr1 = qr0 + 8 * DDIM;
        #pragma unroll
        for (int kk = 0; kk < 4; ++kk) {
            const int c0 = 16 * kk + 2 * tg;
            float2 x0 = *(const float2*)&qr0[c0];
            float2 x1 = *(const float2*)&qr1[c0];
            float2 x2 = *(const float2*)&qr0[c0 + 8];
            float2 x3 = *(const float2*)&qr1[c0 + 8];
            qfrag[rt][kk][0] = packh2(x0.x, x0.y);
            qfrag[rt][kk][1] = packh2(x1.x, x1.y);
            qfrag[rt][kk][2] = packh2(x2.x, x2.y);
            qfrag[rt][kk][3] = packh2(x3.x, x3.y);
        }
    }

    auto issue_kv = [&](int tile, int par) {
        const char* src = kvb + (size_t)tile * TILE_BYTES;
        const uint32_t dst = sb + par * TILE_BYTES;
        #pragma unroll
        for (int i = 0; i < 8; ++i) {
            const int c = tid + 128 * i;
            cpa16(dst + 16 * c, src + 16 * c);
        }
        if (tid < 64) {
            const int c = tid + 1024;
            cpa16(dst + 16 * c, src + 16 * c);
        }
    };

    issue_kv(0, 0); CP_COMMIT();
    issue_kv(1, 1); CP_COMMIT();

    float oacc[2][8][4];                     // partial O over this warp's 32 keys
    #pragma unroll
    for (int rt = 0; rt < 2; ++rt)
        #pragma unroll
        for (int j = 0; j < 8; ++j)
            #pragma unroll
            for (int c = 0; c < 4; ++c) oacc[rt][j][c] = 0.f;
    float lsum[2][2] = {{0.f, 0.f}, {0.f, 0.f}};

    const float EC = 0.18033688011112042f;   // 0.125 * log2(e)

    for (int t = 0; t < NTILES; ++t) {
        const int par = t & 1;
        const uint32_t* kbuf = smem + par * TILE_W;
        const uint32_t* vbuf = kbuf + KIMG_W;

        CP_WAIT1();
        __syncthreads();

        // ---- S = Q K^T on this warp's 32 keys: 2rt x 4kk x 4jj = 32 mma ----
        float sacc[2][4][4];
        #pragma unroll
        for (int rt = 0; rt < 2; ++rt)
            #pragma unroll
            for (int jj = 0; jj < 4; ++jj)
                #pragma unroll
                for (int c = 0; c < 4; ++c) sacc[rt][jj][c] = 0.f;

        #pragma unroll
        for (int kk = 0; kk < 4; ++kk) {
            const uint32_t* kp = &kbuf[(4 * kk + tg) * SLOTW + 2 * g];
            #pragma unroll
            for (int jj = 0; jj < 4; ++jj) {        // key group 8*(4nh+jj)
                uint2 b2 = *(const uint2*)(kp + 16 * (4 * nh + jj));
                mma_f16(sacc[0][jj], qfrag[0][kk], b2.x, b2.y);
                mma_f16(sacc[1][jj], qfrag[1][kk], b2.x, b2.y);
            }
        }

        // ---- mask + exp: S cols are keys 32nh + 8jj + 2tg {,+1} ----
        uint2 pr[2][4];
        #pragma unroll
        for (int rt = 0; rt < 2; ++rt) {
            const int r0 = rw + 16 * rt + g;
            const uint32_t w0 = g_maskbits[(size_t)(q0 + r0) * MASKW + 2 * t + nh];
            const uint32_t w1 = g_maskbits[(size_t)(q0 + r0 + 8) * MASKW + 2 * t + nh];
            #pragma unroll
            for (int jj = 0; jj < 4; ++jj) {
                const int sh = 8 * jj + 2 * tg;
                float e00 = ((w0 >> sh) & 1u)       ? ex2f(sacc[rt][jj][0] * EC) : 0.f;
                float e01 = ((w0 >> (sh + 1)) & 1u) ? ex2f(sacc[rt][jj][1] * EC) : 0.f;
                float e10 = ((w1 >> sh) & 1u)       ? ex2f(sacc[rt][jj][2] * EC) : 0.f;
                float e11 = ((w1 >> (sh + 1)) & 1u) ? ex2f(sacc[rt][jj][3] * EC) : 0.f;
                lsum[rt][0] += e00 + e01;
                lsum[rt][1] += e10 + e11;
                pr[rt][jj] = make_uint2(packh2(e00, e01), packh2(e10, e11));
            }
        }

        // ---- O += P V over this warp's keys: 2rt x 2i x 8j = 32 mma ----
        #pragma unroll
        for (int i = 0; i < 2; ++i) {              // k16 step over keys 32nh+16i..
            const int kkv = 2 * nh + i;            // V image slot group
            uint32_t a0[4] = { pr[0][2*i].x, pr[0][2*i].y, pr[0][2*i+1].x, pr[0][2*i+1].y };
            uint32_t a1[4] = { pr[1][2*i].x, pr[1][2*i].y, pr[1][2*i+1].x, pr[1][2*i+1].y };
            const uint32_t* vp = &vbuf[(4 * kkv + tg) * SLOTW + 2 * g];
            #pragma unroll
            for (int j = 0; j < 8; ++j) {
                uint2 b2 = *(const uint2*)(vp + 16 * j);
                mma_f16(oacc[0][j], a0, b2.x, b2.y);
                mma_f16(oacc[1][j], a1, b2.x, b2.y);
            }
        }

        __syncthreads();
        if (t + 2 < NTILES) issue_kv(t + 2, par);
        CP_COMMIT();
    }

    // ---- end: reduce the two key-halves (O partials and l) via smem ----
    // all cp.async retired (last issue was tile 31, waited at t=31); smem is free
    __syncthreads();
    float* Ored = (float*)smem;                  // [64][64]
    float* lred = Ored + 64 * 64;                // [64]

    // tg-lane reduce l (rows are shared by the two nh warps of this mg)
    #pragma unroll
    for (int rt = 0; rt < 2; ++rt) {
        lsum[rt][0] += __shfl_xor_sync(0xffffffffu, lsum[rt][0], 1);
        lsum[rt][0] += __shfl_xor_sync(0xffffffffu, lsum[rt][0], 2);
        lsum[rt][1] += __shfl_xor_sync(0xffffffffu, lsum[rt][1], 1);
        lsum[rt][1] += __shfl_xor_sync(0xffffffffu, lsum[rt][1], 2);
    }

    if (nh == 0) {   // store partials
        #pragma unroll
        for (int rt = 0; rt < 2; ++rt) {
            const int r0 = rw + 16 * rt + g;
            if (tg == 0) { lred[r0] = lsum[rt][0]; lred[r0 + 8] = lsum[rt][1]; }
            #pragma unroll
            for (int j = 0; j < 8; ++j) {
                *(float2*)&Ored[r0 * 64 + 8 * j + 2 * tg] =
                    make_float2(oacc[rt][j][0], oacc[rt][j][1]);
                *(float2*)&Ored[(r0 + 8) * 64 + 8 * j + 2 * tg] =
                    make_float2(oacc[rt][j][2], oacc[rt][j][3]);
            }
        }
    }
    __syncthreads();
    if (nh == 1) {   // add own partials, normalize, write out
        #pragma unroll
        for (int rt = 0; rt < 2; ++rt) {
            const int r0 = rw + 16 * rt + g;
            const float inv0 = 1.f / (lred[r0] + lsum[rt][0]);
            const float inv1 = 1.f / (lred[r0 + 8] + lsum[rt][1]);
            #pragma unroll
            for (int j = 0; j < 8; ++j) {
                float2 p0 = *(float2*)&Ored[r0 * 64 + 8 * j + 2 * tg];
                float2 p1 = *(float2*)&Ored[(r0 + 8) * 64 + 8 * j + 2 * tg];
                float2 o0 = make_float2((p0.x + oacc[rt][j][0]) * inv0,
                                        (p0.y + oacc[rt][j][1]) * inv0);
                float2 o1 = make_float2((p1.x + oacc[rt][j][2]) * inv1,
                                        (p1.y + oacc[rt][j][3]) * inv1);
                *(float2*)&ob[(size_t)(q0 + r0) * DDIM + 8 * j + 2 * tg] = o0;
                *(float2*)&ob[(size_t)(q0 + r0 + 8) * DDIM + 8 * j + 2 * tg] = o1;
            }
        }
    }
}

// ---------------- launch ----------------
extern "C" void kernel_launch(void* const* d_in, const int* in_sizes, int n_in,
                              void* d_out, int out_size) {
    const float* q = (const float*)d_in[0];
    const float* k = (const float*)d_in[1];
    const float* v = (const float*)d_in[2];
    const int*   m = (const int*)d_in[3];
    float* out = (float*)d_out;

    mask_bits_kernel<<<(S_LEN * MASKW) / 256, 256>>>(m);
    kv_pack_kernel<<<dim3(NTILES, HEADS), 256>>>(k, v);

    dim3 grid(S_LEN / BQ, HEADS);
    fa_f16s_kernel<<<grid, 128>>>(q, out);
}

// round 13
// speedup vs baseline: 1.1855x; 1.1855x over previous
#include <cuda_runtime.h>
#include <cstdint>

#define S_LEN  2048
#define HEADS  32
#define DDIM   64
#define BQ     128
#define BK     64
#define NTILES (S_LEN / BK)   // 32
#define MASKW  (S_LEN / 32)   // 64 mask words per row

#define SLOTW  136                    // pair-slot stride in u32 (2*64 + 8 pad)
#define KIMG_W (16 * SLOTW)           // 2176 u32 = 8704 B (one K or V tile image)
#define TILE_W (2 * KIMG_W)           // 4352 u32 = 17408 B (K + V)
#define TILE_BYTES (TILE_W * 4)
#define NBUF   3
#define SMEM_BYTES (NBUF * TILE_BYTES)   // 52224 B (dynamic) -> 2 CTAs/SM (reg-bound)

__device__ uint32_t g_maskbits[S_LEN * MASKW];                 // 512 KB
__device__ uint32_t g_KVp[(size_t)HEADS * NTILES * TILE_W];    // ~17.8 MB packed K+V (fp16)

__device__ __forceinline__ uint32_t packh2(float lo, float hi) {
    uint32_t r;
    asm("cvt.rn.f16x2.f32 %0, %1, %2;" : "=r"(r) : "f"(hi), "f"(lo));
    return r;
}
__device__ __forceinline__ float ex2f(float x) {
    float r;
    asm("ex2.approx.f32 %0, %1;" : "=f"(r) : "f"(x));
    return r;
}
__device__ __forceinline__ void mma_f16(float* d, const uint32_t* a, uint32_t b0, uint32_t b1) {
    asm volatile(
        "mma.sync.aligned.m16n8k16.row.col.f32.f16.f16.f32 "
        "{%0,%1,%2,%3}, {%4,%5,%6,%7}, {%8,%9}, {%0,%1,%2,%3};"
        : "+f"(d[0]), "+f"(d[1]), "+f"(d[2]), "+f"(d[3])
        : "r"(a[0]), "r"(a[1]), "r"(a[2]), "r"(a[3]), "r"(b0), "r"(b1));
}
__device__ __forceinline__ uint32_t smem_u32(const void* p) {
    uint32_t a;
    asm("{ .reg .u64 t; cvta.to.shared.u64 t, %1; cvt.u32.u64 %0, t; }" : "=r"(a) : "l"(p));
    return a;
}
__device__ __forceinline__ void cpa16(uint32_t s, const void* g) {
    asm volatile("cp.async.cg.shared.global [%0], [%1], 16;" :: "r"(s), "l"(g));
}
#define CP_COMMIT() asm volatile("cp.async.commit_group;" ::: "memory")
#define CP_WAIT1()  asm volatile("cp.async.wait_group 1;" ::: "memory")

// ---------------- mask -> bitmask pre-pass (1 thread = 1 word) ----------------
__global__ void mask_bits_kernel(const int* __restrict__ M) {
    const int w = blockIdx.x * 256 + threadIdx.x;
    const int4* p = (const int4*)(M + (size_t)w * 32);
    uint32_t bits = 0;
    #pragma unroll
    for (int i = 0; i < 8; ++i) {
        int4 v = p[i];
        bits |= (v.x != 0 ? 1u : 0u) << (4 * i + 0);
        bits |= (v.y != 0 ? 1u : 0u) << (4 * i + 1);
        bits |= (v.z != 0 ? 1u : 0u) << (4 * i + 2);
        bits |= (v.w != 0 ? 1u : 0u) << (4 * i + 3);
    }
    g_maskbits[w] = bits;
}

// ---------------- K/V pack pre-pass: fp16 pair-slot smem images ----------------
__global__ void kv_pack_kernel(const float* __restrict__ K, const float* __restrict__ V) {
    const int t = blockIdx.x, h = blockIdx.y;
    const int tid = threadIdx.x;
    const int r = tid & 63, sg = tid >> 6;
    const float* kbT = K + (size_t)h * S_LEN * DDIM + (size_t)t * BK * DDIM;
    const float* vbT = V + (size_t)h * S_LEN * DDIM + (size_t)t * BK * DDIM;
    uint32_t* kd = g_KVp + ((size_t)h * NTILES + t) * TILE_W;
    uint32_t* vd = kd + KIMG_W;

    #pragma unroll
    for (int si = 0; si < 4; ++si) {
        const int slot = 4 * si + sg;
        const int kk = slot >> 2, tg = slot & 3;
        const int c0 = 16 * kk + 2 * tg;
        float2 ka = *(const float2*)&kbT[(size_t)r * DDIM + c0];
        float2 kc = *(const float2*)&kbT[(size_t)r * DDIM + c0 + 8];
        *(uint2*)&kd[slot * SLOTW + 2 * r] =
            make_uint2(packh2(ka.x, ka.y), packh2(kc.x, kc.y));
        float v0 = vbT[(size_t)(c0 + 0) * DDIM + r];
        float v1 = vbT[(size_t)(c0 + 1) * DDIM + r];
        float v8 = vbT[(size_t)(c0 + 8) * DDIM + r];
        float v9 = vbT[(size_t)(c0 + 9) * DDIM + r];
        *(uint2*)&vd[slot * SLOTW + 2 * r] =
            make_uint2(packh2(v0, v1), packh2(v8, v9));
    }
}

// ---------------- main kernel: R9 shape + 3-buf 1-sync + prescaled Q ----------
__global__ void __launch_bounds__(256, 2)
fa_f16p_kernel(const float* __restrict__ Q, float* __restrict__ O) {
    extern __shared__ uint32_t smem[];
    const uint32_t sb = smem_u32(smem);

    const int tid  = threadIdx.x;
    const int wid  = tid >> 5, lane = tid & 31;
    const int g    = lane >> 2, tg = lane & 3;
    const int bh   = blockIdx.y;
    const int q0   = blockIdx.x * BQ;
    const int rwg  = wid * 16 + g;           // warp row-g (local, 0..127)

    const float* qb = Q + (size_t)bh * S_LEN * DDIM;
    float*       ob = O + (size_t)bh * S_LEN * DDIM;
    const char*  kvb = (const char*)(g_KVp + (size_t)bh * NTILES * TILE_W);

    // ---- Q fragments with 0.125*log2(e) folded in: exp(s/8) == ex2(sacc) ----
    const float SC = 0.18033688011112042f;
    uint32_t qfrag[4][4];
    {
        const float* qr0 = &qb[(size_t)(q0 + rwg) * DDIM];
        const float* qr1 = &qb[(size_t)(q0 + rwg + 8) * DDIM];
        #pragma unroll
        for (int kk = 0; kk < 4; ++kk) {
            const int c0 = 16 * kk + 2 * tg;
            float2 x0 = *(const float2*)&qr0[c0];
            float2 x1 = *(const float2*)&qr1[c0];
            float2 x2 = *(const float2*)&qr0[c0 + 8];
            float2 x3 = *(const float2*)&qr1[c0 + 8];
            qfrag[kk][0] = packh2(x0.x * SC, x0.y * SC);
            qfrag[kk][1] = packh2(x1.x * SC, x1.y * SC);
            qfrag[kk][2] = packh2(x2.x * SC, x2.y * SC);
            qfrag[kk][3] = packh2(x3.x * SC, x3.y * SC);
        }
    }

    auto issue_kv = [&](int tile, int buf) {
        const char* src = kvb + (size_t)tile * TILE_BYTES;
        const uint32_t dst = sb + buf * TILE_BYTES;
        #pragma unroll
        for (int i = 0; i < 4; ++i) {
            const int c = tid + 256 * i;
            cpa16(dst + 16 * c, src + 16 * c);
        }
        if (tid < 64) {
            const int c = tid + 1024;
            cpa16(dst + 16 * c, src + 16 * c);
        }
    };

    issue_kv(0, 0); CP_COMMIT();
    issue_kv(1, 1); CP_COMMIT();

    float oacc[8][4];
    #pragma unroll
    for (int j = 0; j < 8; ++j)
        #pragma unroll
        for (int c = 0; c < 4; ++c) oacc[j][c] = 0.f;
    float lsum0 = 0.f, lsum1 = 0.f;

    int buf = 0;
    for (int t = 0; t < NTILES; ++t) {
        const uint32_t* kbuf = smem + buf * TILE_W;
        const uint32_t* vbuf = kbuf + KIMG_W;

        CP_WAIT1();          // tile t's copy group complete
        __syncthreads();     // all warps past tile t-1 (so buf (t+2)%3 is free)

        // prefetch tile t+2 into the buffer last read at tile t-1
        const int nbuf = (buf + 2 >= NBUF) ? buf + 2 - NBUF : buf + 2;
        if (t + 2 < NTILES) issue_kv(t + 2, nbuf);
        CP_COMMIT();

        // ---- S = Q K^T : warp tile 16 x 64, 32 mma ----
        float sacc[8][4];
        #pragma unroll
        for (int j = 0; j < 8; ++j)
            #pragma unroll
            for (int c = 0; c < 4; ++c) sacc[j][c] = 0.f;

        #pragma unroll
        for (int kk = 0; kk < 4; ++kk) {
            const uint32_t* kp = &kbuf[(4 * kk + tg) * SLOTW + 2 * g];
            #pragma unroll
            for (int j = 0; j < 8; ++j) {
                uint2 b2 = *(const uint2*)(kp + 16 * j);
                mma_f16(sacc[j], qfrag[kk], b2.x, b2.y);
            }
        }

        // ---- mask + exp (bare ex2): S cols are keys {8j+2tg, 8j+2tg+1} ----
        uint2 pr[8];
        {
            const uint2 mw0 = *(const uint2*)&g_maskbits[(size_t)(q0 + rwg) * MASKW + 2 * t];
            const uint2 mw1 = *(const uint2*)&g_maskbits[(size_t)(q0 + rwg + 8) * MASKW + 2 * t];
            const uint32_t s0x = mw0.x >> (2 * tg), s0y = mw0.y >> (2 * tg);
            const uint32_t s1x = mw1.x >> (2 * tg), s1y = mw1.y >> (2 * tg);
            #pragma unroll
            for (int j = 0; j < 8; ++j) {
                const uint32_t w0 = (j < 4) ? s0x : s0y;
                const uint32_t w1 = (j < 4) ? s1x : s1y;
                const int sh = (j & 3) << 3;          // compile-time per j
                float e00 = ((w0 >> sh) & 1u)       ? ex2f(sacc[j][0]) : 0.f;
                float e01 = ((w0 >> (sh + 1)) & 1u) ? ex2f(sacc[j][1]) : 0.f;
                float e10 = ((w1 >> sh) & 1u)       ? ex2f(sacc[j][2]) : 0.f;
                float e11 = ((w1 >> (sh + 1)) & 1u) ? ex2f(sacc[j][3]) : 0.f;
                lsum0 += e00 + e01;
                lsum1 += e10 + e11;
                pr[j] = make_uint2(packh2(e00, e01), packh2(e10, e11));
            }
        }

        // ---- O += P V : A-frags are pr[2kk],pr[2kk+1] verbatim, 32 mma ----
        #pragma unroll
        for (int kk = 0; kk < 4; ++kk) {
            uint32_t a[4] = { pr[2*kk].x, pr[2*kk].y, pr[2*kk+1].x, pr[2*kk+1].y };
            const uint32_t* vp = &vbuf[(4 * kk + tg) * SLOTW + 2 * g];
            #pragma unroll
            for (int j = 0; j < 8; ++j) {
                uint2 b2 = *(const uint2*)(vp + 16 * j);
                mma_f16(oacc[j], a, b2.x, b2.y);
            }
        }

        buf = (buf + 1 >= NBUF) ? 0 : buf + 1;
    }

    // ---- reduce l across the 4 tg lanes (rows are warp-private) ----
    lsum0 += __shfl_xor_sync(0xffffffffu, lsum0, 1);
    lsum0 += __shfl_xor_sync(0xffffffffu, lsum0, 2);
    lsum1 += __shfl_xor_sync(0xffffffffu, lsum1, 1);
    lsum1 += __shfl_xor_sync(0xffffffffu, lsum1, 2);
    const float inv0 = 1.f / lsum0;
    const float inv1 = 1.f / lsum1;

    // ---- write O ----
    #pragma unroll
    for (int j = 0; j < 8; ++j) {
        float2 o0 = make_float2(oacc[j][0] * inv0, oacc[j][1] * inv0);
        float2 o1 = make_float2(oacc[j][2] * inv1, oacc[j][3] * inv1);
        *(float2*)&ob[(size_t)(q0 + rwg) * DDIM + 8 * j + 2 * tg] = o0;
        *(float2*)&ob[(size_t)(q0 + rwg + 8) * DDIM + 8 * j + 2 * tg] = o1;
    }
}

// ---------------- launch ----------------
extern "C" void kernel_launch(void* const* d_in, const int* in_sizes, int n_in,
                              void* d_out, int out_size) {
    const float* q = (const float*)d_in[0];
    const float* k = (const float*)d_in[1];
    const float* v = (const float*)d_in[2];
    const int*   m = (const int*)d_in[3];
    float* out = (float*)d_out;

    mask_bits_kernel<<<(S_LEN * MASKW) / 256, 256>>>(m);
    kv_pack_kernel<<<dim3(NTILES, HEADS), 256>>>(k, v);

    cudaFuncSetAttribute(fa_f16p_kernel,
                         cudaFuncAttributeMaxDynamicSharedMemorySize, SMEM_BYTES);
    dim3 grid(S_LEN / BQ, HEADS);
    fa_f16p_kernel<<<grid, 256, SMEM_BYTES>>>(q, out);
}

// round 14
// speedup vs baseline: 1.3625x; 1.1493x over previous
#include <cuda_runtime.h>
#include <cstdint>

#define S_LEN  2048
#define HEADS  32
#define DDIM   64
#define BQ     128
#define BK     64
#define NTILES (S_LEN / BK)   // 32
#define MASKW  (S_LEN / 32)   // 64 mask words per row

#define SLOTW  136                    // pair-slot stride in u32 (2*64 + 8 pad)
#define KIMG_W (16 * SLOTW)           // 2176 u32 = 8704 B (one K or V tile image)
#define TILE_W (2 * KIMG_W)           // 4352 u32 = 17408 B (K + V)
#define TILE_BYTES (TILE_W * 4)
#define NBUF   3
#define SMEM_BYTES (NBUF * TILE_BYTES)   // 52224 B -> 2 CTAs/SM (reg-bound)

#define MASK_BLOCKS ((S_LEN * MASKW) / 256)   // 512
#define KV_BLOCKS   (NTILES * HEADS)          // 1024

__device__ uint32_t g_maskbits[S_LEN * MASKW];                 // 512 KB
__device__ uint32_t g_KVp[(size_t)HEADS * NTILES * TILE_W];    // ~17.8 MB packed K+V (fp16)

__device__ __forceinline__ uint32_t packh2(float lo, float hi) {
    uint32_t r;
    asm("cvt.rn.f16x2.f32 %0, %1, %2;" : "=r"(r) : "f"(hi), "f"(lo));
    return r;
}
__device__ __forceinline__ uint32_t h2ex2(uint32_t x) {   // 2^x on both f16 halves
    uint32_t r;
    asm("ex2.approx.f16x2 %0, %1;" : "=r"(r) : "r"(x));
    return r;
}
__device__ __forceinline__ void mma_f16(float* d, const uint32_t* a, uint32_t b0, uint32_t b1) {
    asm volatile(
        "mma.sync.aligned.m16n8k16.row.col.f32.f16.f16.f32 "
        "{%0,%1,%2,%3}, {%4,%5,%6,%7}, {%8,%9}, {%0,%1,%2,%3};"
        : "+f"(d[0]), "+f"(d[1]), "+f"(d[2]), "+f"(d[3])
        : "r"(a[0]), "r"(a[1]), "r"(a[2]), "r"(a[3]), "r"(b0), "r"(b1));
}
__device__ __forceinline__ uint32_t smem_u32(const void* p) {
    uint32_t a;
    asm("{ .reg .u64 t; cvta.to.shared.u64 t, %1; cvt.u32.u64 %0, t; }" : "=r"(a) : "l"(p));
    return a;
}
__device__ __forceinline__ void cpa16(uint32_t s, const void* g) {
    asm volatile("cp.async.cg.shared.global [%0], [%1], 16;" :: "r"(s), "l"(g));
}
#define CP_COMMIT() asm volatile("cp.async.commit_group;" ::: "memory")
#define CP_WAIT1()  asm volatile("cp.async.wait_group 1;" ::: "memory")

// ---------------- merged prep: mask bits + K/V fp16 pack in one launch --------
__global__ void prep_kernel(const int* __restrict__ M,
                            const float* __restrict__ K, const float* __restrict__ V) {
    if (blockIdx.x < MASK_BLOCKS) {
        const int w = blockIdx.x * 256 + threadIdx.x;
        const int4* p = (const int4*)(M + (size_t)w * 32);
        uint32_t bits = 0;
        #pragma unroll
        for (int i = 0; i < 8; ++i) {
            int4 v = p[i];
            bits |= (v.x != 0 ? 1u : 0u) << (4 * i + 0);
            bits |= (v.y != 0 ? 1u : 0u) << (4 * i + 1);
            bits |= (v.z != 0 ? 1u : 0u) << (4 * i + 2);
            bits |= (v.w != 0 ? 1u : 0u) << (4 * i + 3);
        }
        g_maskbits[w] = bits;
    } else {
        const int b = blockIdx.x - MASK_BLOCKS;
        const int t = b & (NTILES - 1), h = b >> 5;
        const int tid = threadIdx.x;
        const int r = tid & 63, sg = tid >> 6;
        const float* kbT = K + (size_t)h * S_LEN * DDIM + (size_t)t * BK * DDIM;
        const float* vbT = V + (size_t)h * S_LEN * DDIM + (size_t)t * BK * DDIM;
        uint32_t* kd = g_KVp + ((size_t)h * NTILES + t) * TILE_W;
        uint32_t* vd = kd + KIMG_W;
        #pragma unroll
        for (int si = 0; si < 4; ++si) {
            const int slot = 4 * si + sg;
            const int kk = slot >> 2, tg = slot & 3;
            const int c0 = 16 * kk + 2 * tg;
            float2 ka = *(const float2*)&kbT[(size_t)r * DDIM + c0];
            float2 kc = *(const float2*)&kbT[(size_t)r * DDIM + c0 + 8];
            *(uint2*)&kd[slot * SLOTW + 2 * r] =
                make_uint2(packh2(ka.x, ka.y), packh2(kc.x, kc.y));
            float v0 = vbT[(size_t)(c0 + 0) * DDIM + r];
            float v1 = vbT[(size_t)(c0 + 1) * DDIM + r];
            float v8 = vbT[(size_t)(c0 + 8) * DDIM + r];
            float v9 = vbT[(size_t)(c0 + 9) * DDIM + r];
            *(uint2*)&vd[slot * SLOTW + 2 * r] =
                make_uint2(packh2(v0, v1), packh2(v8, v9));
        }
    }
}

// ---------------- main kernel ----------------
__global__ void __launch_bounds__(256, 2)
fa_f16x_kernel(const float* __restrict__ Q, float* __restrict__ O) {
    extern __shared__ uint32_t smem[];
    const uint32_t sb = smem_u32(smem);

    const int tid  = threadIdx.x;
    const int wid  = tid >> 5, lane = tid & 31;
    const int g    = lane >> 2, tg = lane & 3;
    const int bh   = blockIdx.y;
    const int q0   = blockIdx.x * BQ;
    const int rwg  = wid * 16 + g;

    const float* qb = Q + (size_t)bh * S_LEN * DDIM;
    float*       ob = O + (size_t)bh * S_LEN * DDIM;
    const char*  kvb = (const char*)(g_KVp + (size_t)bh * NTILES * TILE_W);

    // ---- Q fragments, 0.125*log2(e) prescaled: exp(s/8) == ex2(sacc) ----
    const float SC = 0.18033688011112042f;
    uint32_t qfrag[4][4];
    {
        const float* qr0 = &qb[(size_t)(q0 + rwg) * DDIM];
        const float* qr1 = &qb[(size_t)(q0 + rwg + 8) * DDIM];
        #pragma unroll
        for (int kk = 0; kk < 4; ++kk) {
            const int c0 = 16 * kk + 2 * tg;
            float2 x0 = *(const float2*)&qr0[c0];
            float2 x1 = *(const float2*)&qr1[c0];
            float2 x2 = *(const float2*)&qr0[c0 + 8];
            float2 x3 = *(const float2*)&qr1[c0 + 8];
            qfrag[kk][0] = packh2(x0.x * SC, x0.y * SC);
            qfrag[kk][1] = packh2(x1.x * SC, x1.y * SC);
            qfrag[kk][2] = packh2(x2.x * SC, x2.y * SC);
            qfrag[kk][3] = packh2(x3.x * SC, x3.y * SC);
        }
    }

    auto issue_kv = [&](int tile, int buf) {
        const char* src = kvb + (size_t)tile * TILE_BYTES;
        const uint32_t dst = sb + buf * TILE_BYTES;
        #pragma unroll
        for (int i = 0; i < 4; ++i) {
            const int c = tid + 256 * i;
            cpa16(dst + 16 * c, src + 16 * c);
        }
        if (tid < 64) {
            const int c = tid + 1024;
            cpa16(dst + 16 * c, src + 16 * c);
        }
    };

    issue_kv(0, 0); CP_COMMIT();
    issue_kv(1, 1); CP_COMMIT();

    float oacc[8][4];
    #pragma unroll
    for (int j = 0; j < 8; ++j)
        #pragma unroll
        for (int c = 0; c < 4; ++c) oacc[j][c] = 0.f;
    float lacc[4] = {0.f, 0.f, 0.f, 0.f};       // row sums via ones-mma
    const uint32_t ONES = 0x3C003C00u;           // {1.0h, 1.0h}

    int buf = 0;
    for (int t = 0; t < NTILES; ++t) {
        const uint32_t* kbuf = smem + buf * TILE_W;
        const uint32_t* vbuf = kbuf + KIMG_W;

        CP_WAIT1();
        __syncthreads();

        const int nbuf = (buf + 2 >= NBUF) ? buf + 2 - NBUF : buf + 2;
        if (t + 2 < NTILES) issue_kv(t + 2, nbuf);
        CP_COMMIT();

        // ---- S = Q K^T : 32 mma ----
        float sacc[8][4];
        #pragma unroll
        for (int j = 0; j < 8; ++j)
            #pragma unroll
            for (int c = 0; c < 4; ++c) sacc[j][c] = 0.f;

        #pragma unroll
        for (int kk = 0; kk < 4; ++kk) {
            const uint32_t* kp = &kbuf[(4 * kk + tg) * SLOTW + 2 * g];
            #pragma unroll
            for (int j = 0; j < 8; ++j) {
                uint2 b2 = *(const uint2*)(kp + 16 * j);
                mma_f16(sacc[j], qfrag[kk], b2.x, b2.y);
            }
        }

        // ---- pack -> ex2.f16x2 -> AND-mask : P fragments directly ----
        uint2 pr[8];
        {
            const uint2 mw0 = *(const uint2*)&g_maskbits[(size_t)(q0 + rwg) * MASKW + 2 * t];
            const uint2 mw1 = *(const uint2*)&g_maskbits[(size_t)(q0 + rwg + 8) * MASKW + 2 * t];
            const uint32_t s0x = mw0.x >> (2 * tg), s0y = mw0.y >> (2 * tg);
            const uint32_t s1x = mw1.x >> (2 * tg), s1y = mw1.y >> (2 * tg);
            #pragma unroll
            for (int j = 0; j < 8; ++j) {
                const uint32_t w0 = (j < 4) ? s0x : s0y;
                const uint32_t w1 = (j < 4) ? s1x : s1y;
                const int sh = (j & 3) << 3;
                const uint32_t m0 = (((w0 >> sh) & 1u) * 0xFFFFu)
                                  | (((w0 >> (sh + 1)) & 1u) * 0xFFFF0000u);
                const uint32_t m1 = (((w1 >> sh) & 1u) * 0xFFFFu)
                                  | (((w1 >> (sh + 1)) & 1u) * 0xFFFF0000u);
                uint32_t e0 = h2ex2(packh2(sacc[j][0], sacc[j][1])) & m0;
                uint32_t e1 = h2ex2(packh2(sacc[j][2], sacc[j][3])) & m1;
                pr[j] = make_uint2(e0, e1);
            }
        }

        // ---- O += P V (32 mma) and l += P 1 (4 mma) ----
        #pragma unroll
        for (int kk = 0; kk < 4; ++kk) {
            uint32_t a[4] = { pr[2*kk].x, pr[2*kk].y, pr[2*kk+1].x, pr[2*kk+1].y };
            const uint32_t* vp = &vbuf[(4 * kk + tg) * SLOTW + 2 * g];
            #pragma unroll
            for (int j = 0; j < 8; ++j) {
                uint2 b2 = *(const uint2*)(vp + 16 * j);
                mma_f16(oacc[j], a, b2.x, b2.y);
            }
            mma_f16(lacc, a, ONES, ONES);      // row sums: every col identical
        }

        buf = (buf + 1 >= NBUF) ? 0 : buf + 1;
    }

    // ---- normalize (lacc[0]/lacc[2] are full row sums; no reduce needed) ----
    const float inv0 = 1.f / lacc[0];
    const float inv1 = 1.f / lacc[2];

    #pragma unroll
    for (int j = 0; j < 8; ++j) {
        float2 o0 = make_float2(oacc[j][0] * inv0, oacc[j][1] * inv0);
        float2 o1 = make_float2(oacc[j][2] * inv1, oacc[j][3] * inv1);
        *(float2*)&ob[(size_t)(q0 + rwg) * DDIM + 8 * j + 2 * tg] = o0;
        *(float2*)&ob[(size_t)(q0 + rwg + 8) * DDIM + 8 * j + 2 * tg] = o1;
    }
}

// ---------------- launch ----------------
extern "C" void kernel_launch(void* const* d_in, const int* in_sizes, int n_in,
                              void* d_out, int out_size) {
    const float* q = (const float*)d_in[0];
    const float* k = (const float*)d_in[1];
    const float* v = (const float*)d_in[2];
    const int*   m = (const int*)d_in[3];
    float* out = (float*)d_out;

    prep_kernel<<<MASK_BLOCKS + KV_BLOCKS, 256>>>(m, k, v);

    cudaFuncSetAttribute(fa_f16x_kernel,
                         cudaFuncAttributeMaxDynamicSharedMemorySize, SMEM_BYTES);
    dim3 grid(S_LEN / BQ, HEADS);
    fa_f16x_kernel<<<grid, 256, SMEM_BYTES>>>(q, out);
}

// round 15
// speedup vs baseline: 1.3676x; 1.0037x over previous
#include <cuda_runtime.h>
#include <cstdint>

#define S_LEN  2048
#define HEADS  32
#define DDIM   64
#define BQ     128
#define BK     64
#define NTILES (S_LEN / BK)   // 32
#define MASKW  (S_LEN / 32)   // 64 mask words per row

// LDS.128-friendly image: per kk region, 4 tg-slots of 132 u32;
// unit(j,g) = 2 u32 at offset 2j + 16g  (conflict-free quarter-warp phases)
#define TGSLOT 132
#define KKREG  (4 * TGSLOT)           // 528 u32
#define KIMG_W (4 * KKREG)            // 2112 u32 = 8448 B (one K or V image)
#define TILE_W (2 * KIMG_W)           // 4224 u32 = 16896 B (K + V)
#define TILE_BYTES (TILE_W * 4)
#define NBUF   3
#define SMEM_BYTES (NBUF * TILE_BYTES)   // 50688 B -> 2 CTAs/SM (reg-bound)

#define MASK_BLOCKS ((S_LEN * MASKW) / 256)   // 512
#define KV_BLOCKS   (NTILES * HEADS)          // 1024

__device__ uint32_t g_maskbits[S_LEN * MASKW];                 // 512 KB
__device__ uint32_t g_KVp[(size_t)HEADS * NTILES * TILE_W];    // ~17.3 MB packed K+V (fp16)

__device__ __forceinline__ uint32_t packh2(float lo, float hi) {
    uint32_t r;
    asm("cvt.rn.f16x2.f32 %0, %1, %2;" : "=r"(r) : "f"(hi), "f"(lo));
    return r;
}
__device__ __forceinline__ uint32_t h2ex2(uint32_t x) {   // 2^x on both f16 halves
    uint32_t r;
    asm("ex2.approx.f16x2 %0, %1;" : "=r"(r) : "r"(x));
    return r;
}
__device__ __forceinline__ void mma_f16(float* d, const uint32_t* a, uint32_t b0, uint32_t b1) {
    asm volatile(
        "mma.sync.aligned.m16n8k16.row.col.f32.f16.f16.f32 "
        "{%0,%1,%2,%3}, {%4,%5,%6,%7}, {%8,%9}, {%0,%1,%2,%3};"
        : "+f"(d[0]), "+f"(d[1]), "+f"(d[2]), "+f"(d[3])
        : "r"(a[0]), "r"(a[1]), "r"(a[2]), "r"(a[3]), "r"(b0), "r"(b1));
}
__device__ __forceinline__ uint32_t smem_u32(const void* p) {
    uint32_t a;
    asm("{ .reg .u64 t; cvta.to.shared.u64 t, %1; cvt.u32.u64 %0, t; }" : "=r"(a) : "l"(p));
    return a;
}
__device__ __forceinline__ void cpa16(uint32_t s, const void* g) {
    asm volatile("cp.async.cg.shared.global [%0], [%1], 16;" :: "r"(s), "l"(g));
}
#define CP_COMMIT() asm volatile("cp.async.commit_group;" ::: "memory")
#define CP_WAIT1()  asm volatile("cp.async.wait_group 1;" ::: "memory")

// ---------------- merged prep: mask bits + K/V fp16 pack (new layout) ---------
__global__ void prep_kernel(const int* __restrict__ M,
                            const float* __restrict__ K, const float* __restrict__ V) {
    if (blockIdx.x < MASK_BLOCKS) {
        const int w = blockIdx.x * 256 + threadIdx.x;
        const int4* p = (const int4*)(M + (size_t)w * 32);
        uint32_t bits = 0;
        #pragma unroll
        for (int i = 0; i < 8; ++i) {
            int4 v = p[i];
            bits |= (v.x != 0 ? 1u : 0u) << (4 * i + 0);
            bits |= (v.y != 0 ? 1u : 0u) << (4 * i + 1);
            bits |= (v.z != 0 ? 1u : 0u) << (4 * i + 2);
            bits |= (v.w != 0 ? 1u : 0u) << (4 * i + 3);
        }
        g_maskbits[w] = bits;
    } else {
        const int b = blockIdx.x - MASK_BLOCKS;
        const int t = b & (NTILES - 1), h = b >> 5;
        const int tid = threadIdx.x;
        const int g = tid & 7, j = (tid >> 3) & 7, tg = tid >> 6;
        const float* kbT = K + (size_t)h * S_LEN * DDIM + (size_t)t * BK * DDIM;
        const float* vbT = V + (size_t)h * S_LEN * DDIM + (size_t)t * BK * DDIM;
        uint32_t* kd = g_KVp + ((size_t)h * NTILES + t) * TILE_W;
        uint32_t* vd = kd + KIMG_W;
        #pragma unroll
        for (int kk = 0; kk < 4; ++kk) {
            const int off = kk * KKREG + tg * TGSLOT + 2 * j + 16 * g;
            // K unit: key row r = g+8j, cols 16kk+2tg (+1), and +8 (+9)
            const int r = g + 8 * j, c0 = 16 * kk + 2 * tg;
            float2 ka = *(const float2*)&kbT[(size_t)r * DDIM + c0];
            float2 kc = *(const float2*)&kbT[(size_t)r * DDIM + c0 + 8];
            kd[off]     = packh2(ka.x, ka.y);
            kd[off + 1] = packh2(kc.x, kc.y);
            // V unit: out col n = g+8j, key rows 16kk+2tg (+1), and +8 (+9)
            const int n = g + 8 * j, kr = 16 * kk + 2 * tg;
            float v0 = vbT[(size_t)(kr + 0) * DDIM + n];
            float v1 = vbT[(size_t)(kr + 1) * DDIM + n];
            float v8 = vbT[(size_t)(kr + 8) * DDIM + n];
            float v9 = vbT[(size_t)(kr + 9) * DDIM + n];
            vd[off]     = packh2(v0, v1);
            vd[off + 1] = packh2(v8, v9);
        }
    }
}

// ---------------- main kernel ----------------
__global__ void __launch_bounds__(256, 2)
fa_f16v_kernel(const float* __restrict__ Q, float* __restrict__ O) {
    extern __shared__ uint32_t smem[];
    const uint32_t sb = smem_u32(smem);

    const int tid  = threadIdx.x;
    const int wid  = tid >> 5, lane = tid & 31;
    const int g    = lane >> 2, tg = lane & 3;
    const int bh   = blockIdx.y;
    const int q0   = blockIdx.x * BQ;
    const int rwg  = wid * 16 + g;

    const float* qb = Q + (size_t)bh * S_LEN * DDIM;
    float*       ob = O + (size_t)bh * S_LEN * DDIM;
    const char*  kvb = (const char*)(g_KVp + (size_t)bh * NTILES * TILE_W);

    // ---- Q fragments, 0.125*log2(e) prescaled ----
    const float SC = 0.18033688011112042f;
    uint32_t qfrag[4][4];
    {
        const float* qr0 = &qb[(size_t)(q0 + rwg) * DDIM];
        const float* qr1 = &qb[(size_t)(q0 + rwg + 8) * DDIM];
        #pragma unroll
        for (int kk = 0; kk < 4; ++kk) {
            const int c0 = 16 * kk + 2 * tg;
            float2 x0 = *(const float2*)&qr0[c0];
            float2 x1 = *(const float2*)&qr1[c0];
            float2 x2 = *(const float2*)&qr0[c0 + 8];
            float2 x3 = *(const float2*)&qr1[c0 + 8];
            qfrag[kk][0] = packh2(x0.x * SC, x0.y * SC);
            qfrag[kk][1] = packh2(x1.x * SC, x1.y * SC);
            qfrag[kk][2] = packh2(x2.x * SC, x2.y * SC);
            qfrag[kk][3] = packh2(x3.x * SC, x3.y * SC);
        }
    }

    auto issue_kv = [&](int tile, int buf) {
        const char* src = kvb + (size_t)tile * TILE_BYTES;
        const uint32_t dst = sb + buf * TILE_BYTES;
        #pragma unroll
        for (int i = 0; i < 4; ++i) {
            const int c = tid + 256 * i;
            cpa16(dst + 16 * c, src + 16 * c);
        }
        if (tid < 32) {
            const int c = tid + 1024;
            cpa16(dst + 16 * c, src + 16 * c);
        }
    };

    issue_kv(0, 0); CP_COMMIT();
    issue_kv(1, 1); CP_COMMIT();

    float oacc[8][4];
    #pragma unroll
    for (int j = 0; j < 8; ++j)
        #pragma unroll
        for (int c = 0; c < 4; ++c) oacc[j][c] = 0.f;
    float lacc[4] = {0.f, 0.f, 0.f, 0.f};
    const uint32_t ONES = 0x3C003C00u;

    int buf = 0;
    for (int t = 0; t < NTILES; ++t) {
        const uint32_t* kbuf = smem + buf * TILE_W;
        const uint32_t* vbuf = kbuf + KIMG_W;

        CP_WAIT1();
        __syncthreads();

        const int nbuf = (buf + 2 >= NBUF) ? buf + 2 - NBUF : buf + 2;
        if (t + 2 < NTILES) issue_kv(t + 2, nbuf);
        CP_COMMIT();

        // ---- S = Q K^T : 16 LDS.128 + 32 mma ----
        float sacc[8][4];
        #pragma unroll
        for (int j = 0; j < 8; ++j)
            #pragma unroll
            for (int c = 0; c < 4; ++c) sacc[j][c] = 0.f;

        #pragma unroll
        for (int kk = 0; kk < 4; ++kk) {
            const uint32_t* kp = &kbuf[kk * KKREG + tg * TGSLOT + 16 * g];
            #pragma unroll
            for (int jp = 0; jp < 4; ++jp) {
                uint4 b = *(const uint4*)(kp + 4 * jp);
                mma_f16(sacc[2 * jp],     qfrag[kk], b.x, b.y);
                mma_f16(sacc[2 * jp + 1], qfrag[kk], b.z, b.w);
            }
        }

        // ---- pack -> ex2.f16x2 -> AND-mask : P fragments directly ----
        uint2 pr[8];
        {
            const uint2 mw0 = *(const uint2*)&g_maskbits[(size_t)(q0 + rwg) * MASKW + 2 * t];
            const uint2 mw1 = *(const uint2*)&g_maskbits[(size_t)(q0 + rwg + 8) * MASKW + 2 * t];
            const uint32_t s0x = mw0.x >> (2 * tg), s0y = mw0.y >> (2 * tg);
            const uint32_t s1x = mw1.x >> (2 * tg), s1y = mw1.y >> (2 * tg);
            #pragma unroll
            for (int j = 0; j < 8; ++j) {
                const uint32_t w0 = (j < 4) ? s0x : s0y;
                const uint32_t w1 = (j < 4) ? s1x : s1y;
                const int sh = (j & 3) << 3;
                const uint32_t m0 = (((w0 >> sh) & 1u) * 0xFFFFu)
                                  | (((w0 >> (sh + 1)) & 1u) * 0xFFFF0000u);
                const uint32_t m1 = (((w1 >> sh) & 1u) * 0xFFFFu)
                                  | (((w1 >> (sh + 1)) & 1u) * 0xFFFF0000u);
                uint32_t e0 = h2ex2(packh2(sacc[j][0], sacc[j][1])) & m0;
                uint32_t e1 = h2ex2(packh2(sacc[j][2], sacc[j][3])) & m1;
                pr[j] = make_uint2(e0, e1);
            }
        }

        // ---- O += P V (16 LDS.128 + 32 mma) and l += P 1 (4 mma) ----
        #pragma unroll
        for (int kk = 0; kk < 4; ++kk) {
            uint32_t a[4] = { pr[2*kk].x, pr[2*kk].y, pr[2*kk+1].x, pr[2*kk+1].y };
            const uint32_t* vp = &vbuf[kk * KKREG + tg * TGSLOT + 16 * g];
            #pragma unroll
            for (int jp = 0; jp < 4; ++jp) {
                uint4 b = *(const uint4*)(vp + 4 * jp);
                mma_f16(oacc[2 * jp],     a, b.x, b.y);
                mma_f16(oacc[2 * jp + 1], a, b.z, b.w);
            }
            mma_f16(lacc, a, ONES, ONES);
        }

        buf = (buf + 1 >= NBUF) ? 0 : buf + 1;
    }

    // ---- normalize (lacc[0]/lacc[2] are full row sums) and write O ----
    const float inv0 = 1.f / lacc[0];
    const float inv1 = 1.f / lacc[2];

    #pragma unroll
    for (int j = 0; j < 8; ++j) {
        float2 o0 = make_float2(oacc[j][0] * inv0, oacc[j][1] * inv0);
        float2 o1 = make_float2(oacc[j][2] * inv1, oacc[j][3] * inv1);
        *(float2*)&ob[(size_t)(q0 + rwg) * DDIM + 8 * j + 2 * tg] = o0;
        *(float2*)&ob[(size_t)(q0 + rwg + 8) * DDIM + 8 * j + 2 * tg] = o1;
    }
}

// ---------------- launch ----------------
extern "C" void kernel_launch(void* const* d_in, const int* in_sizes, int n_in,
                              void* d_out, int out_size) {
    const float* q = (const float*)d_in[0];
    const float* k = (const float*)d_in[1];
    const float* v = (const float*)d_in[2];
    const int*   m = (const int*)d_in[3];
    float* out = (float*)d_out;

    prep_kernel<<<MASK_BLOCKS + KV_BLOCKS, 256>>>(m, k, v);

    cudaFuncSetAttribute(fa_f16v_kernel,
                         cudaFuncAttributeMaxDynamicSharedMemorySize, SMEM_BYTES);
    dim3 grid(S_LEN / BQ, HEADS);
    fa_f16v_kernel<<<grid, 256, SMEM_BYTES>>>(q, out);
}

// round 16
// speedup vs baseline: 1.4508x; 1.0608x over previous
#include <cuda_runtime.h>
#include <cstdint>

#define S_LEN  2048
#define HEADS  32
#define DDIM   64
#define BQ     128
#define BK     64
#define NTILES (S_LEN / BK)   // 32
#define MASKW  (S_LEN / 32)   // 64 mask words per row

// frag-major packed image: chunk(kk,jp) = 32 lanes x 16B, K then V
// u8 offset of chunk c, lane ln: (c*32 + ln)*16
#define KIMG_BYTES 8192                    // 16 chunks x 512 B
#define TILE_BYTES (2 * KIMG_BYTES)        // 16384 B (K + V)
#define TILE_U4    (TILE_BYTES / 16)       // 1024 uint4

#define MASK_BLOCKS ((S_LEN * MASKW) / 256)   // 512
#define KV_BLOCKS   (NTILES * HEADS)          // 1024

__device__ uint32_t g_maskbits[S_LEN * MASKW];                     // 512 KB
__device__ uint4    g_KVp[(size_t)HEADS * NTILES * TILE_U4];       // 16.8 MB packed K+V (fp16)

__device__ __forceinline__ uint32_t packh2(float lo, float hi) {
    uint32_t r;
    asm("cvt.rn.f16x2.f32 %0, %1, %2;" : "=r"(r) : "f"(hi), "f"(lo));
    return r;
}
__device__ __forceinline__ uint32_t h2ex2(uint32_t x) {   // 2^x on both f16 halves
    uint32_t r;
    asm("ex2.approx.f16x2 %0, %1;" : "=r"(r) : "r"(x));
    return r;
}
__device__ __forceinline__ void mma_f16(float* d, const uint32_t* a, uint32_t b0, uint32_t b1) {
    asm volatile(
        "mma.sync.aligned.m16n8k16.row.col.f32.f16.f16.f32 "
        "{%0,%1,%2,%3}, {%4,%5,%6,%7}, {%8,%9}, {%0,%1,%2,%3};"
        : "+f"(d[0]), "+f"(d[1]), "+f"(d[2]), "+f"(d[3])
        : "r"(a[0]), "r"(a[1]), "r"(a[2]), "r"(a[3]), "r"(b0), "r"(b1));
}

// ---------------- merged prep: mask bits + K/V fp16 frag-major pack -----------
__global__ void prep_kernel(const int* __restrict__ M,
                            const float* __restrict__ K, const float* __restrict__ V) {
    if (blockIdx.x < MASK_BLOCKS) {
        const int w = blockIdx.x * 256 + threadIdx.x;
        const int4* p = (const int4*)(M + (size_t)w * 32);
        uint32_t bits = 0;
        #pragma unroll
        for (int i = 0; i < 8; ++i) {
            int4 v = p[i];
            bits |= (v.x != 0 ? 1u : 0u) << (4 * i + 0);
            bits |= (v.y != 0 ? 1u : 0u) << (4 * i + 1);
            bits |= (v.z != 0 ? 1u : 0u) << (4 * i + 2);
            bits |= (v.w != 0 ? 1u : 0u) << (4 * i + 3);
        }
        g_maskbits[w] = bits;
    } else {
        const int b = blockIdx.x - MASK_BLOCKS;
        const int t = b & (NTILES - 1), h = b >> 5;
        const int tid = threadIdx.x;
        const float* kbT = K + (size_t)h * S_LEN * DDIM + (size_t)t * BK * DDIM;
        const float* vbT = V + (size_t)h * S_LEN * DDIM + (size_t)t * BK * DDIM;
        uint4* dst = g_KVp + ((size_t)h * NTILES + t) * TILE_U4;

        #pragma unroll
        for (int i = 0; i < 4; ++i) {
            const int idx = tid + 256 * i;           // 0..1023
            const int c  = idx >> 5, ln = idx & 31;  // chunk, lane
            const int g = ln >> 2, tg = ln & 3;
            uint4 w;
            if (c < 16) {
                // K chunk (kk=c>>2, jp=c&3): keys r=g+16jp (+8), cols 16kk+2tg(+1,+8,+9)
                const int kk = c >> 2, jp = c & 3;
                const int r = g + 16 * jp, c0 = 16 * kk + 2 * tg;
                float2 a0 = *(const float2*)&kbT[(size_t)r * DDIM + c0];
                float2 a1 = *(const float2*)&kbT[(size_t)r * DDIM + c0 + 8];
                float2 a2 = *(const float2*)&kbT[(size_t)(r + 8) * DDIM + c0];
                float2 a3 = *(const float2*)&kbT[(size_t)(r + 8) * DDIM + c0 + 8];
                w.x = packh2(a0.x, a0.y);
                w.y = packh2(a1.x, a1.y);
                w.z = packh2(a2.x, a2.y);
                w.w = packh2(a3.x, a3.y);
            } else {
                // V chunk (kk, jp): out cols n=g+16jp (+8), key rows 16kk+2tg(+1,+8,+9)
                const int kk = (c - 16) >> 2, jp = (c - 16) & 3;
                const int n = g + 16 * jp, kr = 16 * kk + 2 * tg;
                float v0 = vbT[(size_t)(kr + 0) * DDIM + n];
                float v1 = vbT[(size_t)(kr + 1) * DDIM + n];
                float v8 = vbT[(size_t)(kr + 8) * DDIM + n];
                float v9 = vbT[(size_t)(kr + 9) * DDIM + n];
                float u0 = vbT[(size_t)(kr + 0) * DDIM + n + 8];
                float u1 = vbT[(size_t)(kr + 1) * DDIM + n + 8];
                float u8 = vbT[(size_t)(kr + 8) * DDIM + n + 8];
                float u9 = vbT[(size_t)(kr + 9) * DDIM + n + 8];
                w.x = packh2(v0, v1);
                w.y = packh2(v8, v9);
                w.z = packh2(u0, u1);
                w.w = packh2(u8, u9);
            }
            dst[idx] = w;
        }
    }
}

// ---------------- main kernel: smem-free, sync-free, direct-LDG fragments -----
__global__ void __launch_bounds__(256, 2)
fa_f16g_kernel(const float* __restrict__ Q, float* __restrict__ O) {
    const int tid  = threadIdx.x;
    const int wid  = tid >> 5, lane = tid & 31;
    const int g    = lane >> 2, tg = lane & 3;
    const int bh   = blockIdx.y;
    const int q0   = blockIdx.x * BQ;
    const int rwg  = wid * 16 + g;

    const float* qb = Q + (size_t)bh * S_LEN * DDIM;
    float*       ob = O + (size_t)bh * S_LEN * DDIM;
    const uint4* kvb = g_KVp + (size_t)bh * NTILES * TILE_U4;

    // ---- Q fragments, 0.125*log2(e) prescaled ----
    const float SC = 0.18033688011112042f;
    uint32_t qfrag[4][4];
    {
        const float* qr0 = &qb[(size_t)(q0 + rwg) * DDIM];
        const float* qr1 = &qb[(size_t)(q0 + rwg + 8) * DDIM];
        #pragma unroll
        for (int kk = 0; kk < 4; ++kk) {
            const int c0 = 16 * kk + 2 * tg;
            float2 x0 = *(const float2*)&qr0[c0];
            float2 x1 = *(const float2*)&qr1[c0];
            float2 x2 = *(const float2*)&qr0[c0 + 8];
            float2 x3 = *(const float2*)&qr1[c0 + 8];
            qfrag[kk][0] = packh2(x0.x * SC, x0.y * SC);
            qfrag[kk][1] = packh2(x1.x * SC, x1.y * SC);
            qfrag[kk][2] = packh2(x2.x * SC, x2.y * SC);
            qfrag[kk][3] = packh2(x3.x * SC, x3.y * SC);
        }
    }

    float oacc[8][4];
    #pragma unroll
    for (int j = 0; j < 8; ++j)
        #pragma unroll
        for (int c = 0; c < 4; ++c) oacc[j][c] = 0.f;
    float lacc[4] = {0.f, 0.f, 0.f, 0.f};
    const uint32_t ONES = 0x3C003C00u;

    const uint2* mrow0 = (const uint2*)&g_maskbits[(size_t)(q0 + rwg) * MASKW];
    const uint2* mrow1 = (const uint2*)&g_maskbits[(size_t)(q0 + rwg + 8) * MASKW];

    for (int t = 0; t < NTILES; ++t) {
        const uint4* kc = kvb + (size_t)t * TILE_U4 + lane;        // K chunks
        const uint4* vc = kc + 512;                                 // V chunks

        // ---- S = Q K^T : 16 coalesced LDG.128 + 32 mma ----
        float sacc[8][4];
        #pragma unroll
        for (int j = 0; j < 8; ++j)
            #pragma unroll
            for (int c = 0; c < 4; ++c) sacc[j][c] = 0.f;

        #pragma unroll
        for (int kk = 0; kk < 4; ++kk) {
            #pragma unroll
            for (int jp = 0; jp < 4; ++jp) {
                uint4 b = kc[(kk * 4 + jp) * 32];
                mma_f16(sacc[2 * jp],     qfrag[kk], b.x, b.y);
                mma_f16(sacc[2 * jp + 1], qfrag[kk], b.z, b.w);
            }
        }

        // ---- pack -> ex2.f16x2 -> AND-mask : P fragments directly ----
        uint2 pr[8];
        {
            const uint2 mw0 = mrow0[t];
            const uint2 mw1 = mrow1[t];
            const uint32_t s0x = mw0.x >> (2 * tg), s0y = mw0.y >> (2 * tg);
            const uint32_t s1x = mw1.x >> (2 * tg), s1y = mw1.y >> (2 * tg);
            #pragma unroll
            for (int j = 0; j < 8; ++j) {
                const uint32_t w0 = (j < 4) ? s0x : s0y;
                const uint32_t w1 = (j < 4) ? s1x : s1y;
                const int sh = (j & 3) << 3;
                const uint32_t m0 = (((w0 >> sh) & 1u) * 0xFFFFu)
                                  | (((w0 >> (sh + 1)) & 1u) * 0xFFFF0000u);
                const uint32_t m1 = (((w1 >> sh) & 1u) * 0xFFFFu)
                                  | (((w1 >> (sh + 1)) & 1u) * 0xFFFF0000u);
                uint32_t e0 = h2ex2(packh2(sacc[j][0], sacc[j][1])) & m0;
                uint32_t e1 = h2ex2(packh2(sacc[j][2], sacc[j][3])) & m1;
                pr[j] = make_uint2(e0, e1);
            }
        }

        // ---- O += P V (16 coalesced LDG.128 + 32 mma) and l += P 1 (4 mma) ----
        #pragma unroll
        for (int kk = 0; kk < 4; ++kk) {
            uint32_t a[4] = { pr[2*kk].x, pr[2*kk].y, pr[2*kk+1].x, pr[2*kk+1].y };
            #pragma unroll
            for (int jp = 0; jp < 4; ++jp) {
                uint4 b = vc[(kk * 4 + jp) * 32];
                mma_f16(oacc[2 * jp],     a, b.x, b.y);
                mma_f16(oacc[2 * jp + 1], a, b.z, b.w);
            }
            mma_f16(lacc, a, ONES, ONES);
        }
    }

    // ---- normalize (lacc[0]/lacc[2] are full row sums) and write O ----
    const float inv0 = 1.f / lacc[0];
    const float inv1 = 1.f / lacc[2];

    #pragma unroll
    for (int j = 0; j < 8; ++j) {
        float2 o0 = make_float2(oacc[j][0] * inv0, oacc[j][1] * inv0);
        float2 o1 = make_float2(oacc[j][2] * inv1, oacc[j][3] * inv1);
        *(float2*)&ob[(size_t)(q0 + rwg) * DDIM + 8 * j + 2 * tg] = o0;
        *(float2*)&ob[(size_t)(q0 + rwg + 8) * DDIM + 8 * j + 2 * tg] = o1;
    }
}

// ---------------- launch ----------------
extern "C" void kernel_launch(void* const* d_in, const int* in_sizes, int n_in,
                              void* d_out, int out_size) {
    const float* q = (const float*)d_in[0];
    const float* k = (const float*)d_in[1];
    const float* v = (const float*)d_in[2];
    const int*   m = (const int*)d_in[3];
    float* out = (float*)d_out;

    prep_kernel<<<MASK_BLOCKS + KV_BLOCKS, 256>>>(m, k, v);

    // no smem: ask for max-L1 carveout
    cudaFuncSetAttribute(fa_f16g_kernel,
                         cudaFuncAttributePreferredSharedMemoryCarveout, 0);
    dim3 grid(S_LEN / BQ, HEADS);
    fa_f16g_kernel<<<grid, 256>>>(q, out);
}